// round 11
// baseline (speedup 1.0000x reference)
#include <cuda_runtime.h>
#include <cuda_bf16.h>
#include <math.h>

// ---------------- problem constants ----------------
#define B_N   32
#define L_N   4096
#define C_N   96
#define GG_N  64
#define NW_N  2048
#define T_N   131072
#define HID_N 384

#define OUT0_ELEMS (T_N * C_N)
#define ATTN_ELEMS (NW_N * 3 * GG_N * GG_N)

#define SCALE_F 0.17677669529663687f  // 32^-0.5

// ---------------- scratch ----------------
__device__ float g_attn_fb[ATTN_ELEMS];  // fallback sink for attn probs

// fragment-packed bf16 weights, uint4 = 2 consecutive k-steps:
//   entry (n8, kq, lane): v.x/v.y = frag(ks=2kq), v.z/v.w = frag(ks=2kq+1)
//   v.x = pack(W[k0][n], W[k0+1][n]), v.y = +8 rows, with
//   n = n8*8 + (lane>>2), k0 = kq*32 + (lane&3)*2 (+kbase)
__device__ uint4 g_wqkv_p4[36 * 3 * 32];     // N=288
__device__ uint4 g_wproj_p4[12 * 3 * 32];    // N=96
__device__ uint4 g_w1_p4[48 * 3 * 32];       // N=384
__device__ uint4 g_w2_p4[4 * 12 * 3 * 32];   // 4 chunks, N=96 each

__device__ __forceinline__ unsigned packbf(float a, float b) {
    __nv_bfloat162 t = __floats2bfloat162_rn(a, b);
    return *(unsigned*)&t;
}

// jobs: qkv 3456, proj 1152, w1 4608, w2 4608 (total 13824)
__global__ void prep_weights(const float* __restrict__ wqkv,
                             const float* __restrict__ wproj,
                             const float* __restrict__ w1,
                             const float* __restrict__ w2) {
    int i = blockIdx.x * 256 + threadIdx.x;
    if (i >= 13824) return;
    const float* src;
    uint4* dst;
    int ld, kbase = 0, idx;
    if (i < 3456)              { src = wqkv;  dst = g_wqkv_p4;  ld = 288; idx = i; }
    else if (i < 4608)         { src = wproj; dst = g_wproj_p4; ld = 96;  idx = i - 3456; }
    else if (i < 9216)         { src = w1;    dst = g_w1_p4;    ld = 384; idx = i - 4608; }
    else                       {
        int j = i - 9216;
        int c = j / 1152;
        src = w2; dst = g_w2_p4 + c * 1152; ld = 96; kbase = c * 96; idx = j - c * 1152;
    }
    int q = idx >> 5, lane = idx & 31;
    int n8 = q / 3, kq = q - n8 * 3;
    int g = lane >> 2, tig = lane & 3;
    int n = n8 * 8 + g;
    int k0 = kbase + kq * 32 + tig * 2;
    uint4 v;
    v.x = packbf(src[(size_t)k0 * ld + n],        src[(size_t)(k0 + 1) * ld + n]);
    v.y = packbf(src[(size_t)(k0 + 8) * ld + n],  src[(size_t)(k0 + 9) * ld + n]);
    v.z = packbf(src[(size_t)(k0 + 16) * ld + n], src[(size_t)(k0 + 17) * ld + n]);
    v.w = packbf(src[(size_t)(k0 + 24) * ld + n], src[(size_t)(k0 + 25) * ld + n]);
    dst[q * 32 + lane] = v;
}

__device__ __forceinline__ int win2tok(int m) {
    int w = m >> 6, t = m & 63;
    int b = w >> 6, rem = w & 63;
    int hy = rem >> 3, wx = rem & 7;
    int gy = t >> 3,  gx = t & 7;
    return b * L_N + (hy * 8 + gy) * 64 + (wx * 8 + gx);
}

__device__ __forceinline__ void mma16(float* c, const unsigned* a, const unsigned* b) {
    asm volatile(
        "mma.sync.aligned.m16n8k16.row.col.f32.bf16.bf16.f32 "
        "{%0,%1,%2,%3}, {%4,%5,%6,%7}, {%8,%9}, {%0,%1,%2,%3};\n"
        : "+f"(c[0]), "+f"(c[1]), "+f"(c[2]), "+f"(c[3])
        : "r"(a[0]), "r"(a[1]), "r"(a[2]), "r"(a[3]), "r"(b[0]), "r"(b[1]));
}

// unpack 8 bf16 (16B-aligned) into 8 floats via one LDS.128
__device__ __forceinline__ void load8bf(float* dst, const __nv_bfloat16* p) {
    uint4 u = *(const uint4*)p;
    __nv_bfloat162 b0 = *(__nv_bfloat162*)&u.x;
    __nv_bfloat162 b1 = *(__nv_bfloat162*)&u.y;
    __nv_bfloat162 b2 = *(__nv_bfloat162*)&u.z;
    __nv_bfloat162 b3 = *(__nv_bfloat162*)&u.w;
    dst[0] = __low2float(b0); dst[1] = __high2float(b0);
    dst[2] = __low2float(b1); dst[3] = __high2float(b1);
    dst[4] = __low2float(b2); dst[5] = __high2float(b2);
    dst[6] = __low2float(b3); dst[7] = __high2float(b3);
}

// ---------------- smem layout (bytes) ----------------
#define SM_AS  0        // 12800: As (LN out, stride 100) / Ps (probs, stride 72)
#define SM_QS  12800    // 12800: Q scaled, stride 100
#define SM_KS  25600    // 12800: K, stride 100
#define SM_VT  38400    // 13824: V^T [c][t], stride 72
#define SM_OS  52224    // 12800: lepe-init then attn-out (stride 100) / Hs
#define SM_XC  65024    // 1024:  softmax exchange float[2][64][2]
#define SM_TOT 66048

__global__ __launch_bounds__(256, 3)
void block_kernel(const float* __restrict__ x,
                  const float* __restrict__ bqkv,
                  const float* __restrict__ wl,
                  const float* __restrict__ bl,
                  const float* __restrict__ bproj,
                  const float* __restrict__ g1,
                  const float* __restrict__ bt1,
                  const float* __restrict__ g2,
                  const float* __restrict__ bt2,
                  const float* __restrict__ b1,
                  const float* __restrict__ b2,
                  float* __restrict__ out,
                  float* __restrict__ attn_out) {
    extern __shared__ char smraw[];
    __nv_bfloat16* As = (__nv_bfloat16*)(smraw + SM_AS);
    __nv_bfloat16* Ps = (__nv_bfloat16*)(smraw + SM_AS);
    __nv_bfloat16* Qs = (__nv_bfloat16*)(smraw + SM_QS);
    __nv_bfloat16* Ks = (__nv_bfloat16*)(smraw + SM_KS);
    __nv_bfloat16* Vt = (__nv_bfloat16*)(smraw + SM_VT);
    __nv_bfloat16* Os = (__nv_bfloat16*)(smraw + SM_OS);
    __nv_bfloat16* Hs = (__nv_bfloat16*)(smraw + SM_OS);
    float*         Xc = (float*)(smraw + SM_XC);

    int w = blockIdx.x;
    int tid = threadIdx.x, lane = tid & 31, wid = tid >> 5;
    int g = lane >> 2, tig = lane & 3;
    // attention mapping
    int mw = (wid >> 1) * 16, wh = wid & 1;
    // GEMM (2 mt x 3 nt) mapping
    int gm = (wid >> 2) * 32;      // row-group base: 0 or 32
    int cgi = wid & 3;             // col-group index 0..3
    int gc = cgi * 24;             // col base

    // ---- phase 0: LN1(x window rows) -> As bf16 ----
    #pragma unroll
    for (int r = 0; r < 8; r++) {
        int t = wid * 8 + r;
        const float* xr = x + (size_t)win2tok(w * 64 + t) * 96;
        float v0 = xr[lane], v1 = xr[lane + 32], v2 = xr[lane + 64];
        float s = v0 + v1 + v2;
        #pragma unroll
        for (int o = 16; o; o >>= 1) s += __shfl_xor_sync(~0u, s, o);
        float m = s * (1.f / 96.f);
        float d0 = v0 - m, d1 = v1 - m, d2 = v2 - m;
        float q = d0 * d0 + d1 * d1 + d2 * d2;
        #pragma unroll
        for (int o = 16; o; o >>= 1) q += __shfl_xor_sync(~0u, q, o);
        float rr = rsqrtf(q * (1.f / 96.f) + 1e-5f);
        As[t * 100 + lane]      = __float2bfloat16(d0 * rr * g1[lane]      + bt1[lane]);
        As[t * 100 + lane + 32] = __float2bfloat16(d1 * rr * g1[lane + 32] + bt1[lane + 32]);
        As[t * 100 + lane + 64] = __float2bfloat16(d2 * rr * g1[lane + 64] + bt1[lane + 64]);
    }
    __syncthreads();

    // ---- phase 1: QKV, warp tile 32 rows x 24 cols ----
    #pragma unroll
    for (int seg = 0; seg < 3; seg++) {
        float acc[2][3][4] = {};
        #pragma unroll
        for (int kq = 0; kq < 3; kq++) {
            uint4 b4[3];
            #pragma unroll
            for (int nt = 0; nt < 3; nt++) {
                int n8 = seg * 12 + cgi * 3 + nt;
                b4[nt] = __ldg(&g_wqkv_p4[(n8 * 3 + kq) * 32 + lane]);
            }
            #pragma unroll
            for (int kh = 0; kh < 2; kh++) {
                int kb = kq * 32 + kh * 16;
                unsigned a[2][4];
                #pragma unroll
                for (int mt = 0; mt < 2; mt++) {
                    int r = gm + mt * 16;
                    a[mt][0] = *(const unsigned*)&As[(r + g)     * 100 + kb + tig * 2];
                    a[mt][1] = *(const unsigned*)&As[(r + g + 8) * 100 + kb + tig * 2];
                    a[mt][2] = *(const unsigned*)&As[(r + g)     * 100 + kb + 8 + tig * 2];
                    a[mt][3] = *(const unsigned*)&As[(r + g + 8) * 100 + kb + 8 + tig * 2];
                }
                #pragma unroll
                for (int mt = 0; mt < 2; mt++)
                    #pragma unroll
                    for (int nt = 0; nt < 3; nt++)
                        mma16(acc[mt][nt], a[mt],
                              ((const unsigned*)&b4[nt]) + kh * 2);
            }
        }
        #pragma unroll
        for (int mt = 0; mt < 2; mt++) {
            #pragma unroll
            for (int nt = 0; nt < 3; nt++) {
                #pragma unroll
                for (int half = 0; half < 2; half++) {
                    int t = gm + mt * 16 + g + half * 8;
                    int c = gc + nt * 8 + tig * 2;
                    float v0 = acc[mt][nt][half * 2 + 0] + bqkv[seg * 96 + c];
                    float v1 = acc[mt][nt][half * 2 + 1] + bqkv[seg * 96 + c + 1];
                    if (seg == 0) {
                        *(__nv_bfloat162*)&Qs[t * 100 + c] =
                            __floats2bfloat162_rn(v0 * SCALE_F, v1 * SCALE_F);
                    } else if (seg == 1) {
                        *(__nv_bfloat162*)&Ks[t * 100 + c] =
                            __floats2bfloat162_rn(v0, v1);
                    } else {
                        Vt[c * 72 + t]       = __float2bfloat16(v0);
                        Vt[(c + 1) * 72 + t] = __float2bfloat16(v1);
                    }
                }
            }
        }
    }
    __syncthreads();

    // ---- phase 1.5: LePE init: Os[t][d] = bf16(bl[d] + conv3x3(V_d)) ----
    #pragma unroll
    for (int j = 0; j < 3; j++) {
        int r = tid * 3 + j;
        int d = r >> 3, gy = r & 7;
        const float* wr = wl + d * 9;
        float w00 = wr[0], w01 = wr[1], w02 = wr[2];
        float w10 = wr[3], w11 = wr[4], w12 = wr[5];
        float w20 = wr[6], w21 = wr[7], w22 = wr[8];
        const __nv_bfloat16* vb = Vt + d * 72;
        float vt[8], vm[8], vbo[8];
        load8bf(vm, vb + gy * 8);
        if (gy > 0) {
            load8bf(vt, vb + (gy - 1) * 8);
        } else {
            for (int q2 = 0; q2 < 8; q2++) vt[q2] = 0.f;
        }
        if (gy < 7) {
            load8bf(vbo, vb + (gy + 1) * 8);
        } else {
            for (int q2 = 0; q2 < 8; q2++) vbo[q2] = 0.f;
        }
        float base = bl[d];
        #pragma unroll
        for (int gx = 0; gx < 8; gx++) {
            float o = base + vt[gx] * w01 + vm[gx] * w11 + vbo[gx] * w21;
            if (gx > 0) o += vt[gx - 1] * w00 + vm[gx - 1] * w10 + vbo[gx - 1] * w20;
            if (gx < 7) o += vt[gx + 1] * w02 + vm[gx + 1] * w12 + vbo[gx + 1] * w22;
            Os[(gy * 8 + gx) * 100 + d] = __float2bfloat16(o);
        }
    }

    // ---- phase 2: per-head attention with register softmax ----
    #pragma unroll
    for (int h = 0; h < 3; h++) {
        int h32 = h * 32;
        int nw2 = wh * 32;
        float sacc[4][4] = {};
        #pragma unroll
        for (int ks = 0; ks < 2; ks++) {
            int kb = h32 + ks * 16;
            unsigned a[4];
            a[0] = *(const unsigned*)&Qs[(mw + g)     * 100 + kb + tig * 2];
            a[1] = *(const unsigned*)&Qs[(mw + g + 8) * 100 + kb + tig * 2];
            a[2] = *(const unsigned*)&Qs[(mw + g)     * 100 + kb + 8 + tig * 2];
            a[3] = *(const unsigned*)&Qs[(mw + g + 8) * 100 + kb + 8 + tig * 2];
            #pragma unroll
            for (int nt = 0; nt < 4; nt++) {
                unsigned b[2];
                int c0 = nw2 + nt * 8 + g;
                b[0] = *(const unsigned*)&Ks[c0 * 100 + kb + tig * 2];
                b[1] = *(const unsigned*)&Ks[c0 * 100 + kb + 8 + tig * 2];
                mma16(sacc[nt], a, b);
            }
        }
        float m0 = -1e30f, m1 = -1e30f;
        #pragma unroll
        for (int nt = 0; nt < 4; nt++) {
            m0 = fmaxf(m0, fmaxf(sacc[nt][0], sacc[nt][1]));
            m1 = fmaxf(m1, fmaxf(sacc[nt][2], sacc[nt][3]));
        }
        m0 = fmaxf(m0, __shfl_xor_sync(~0u, m0, 1));
        m0 = fmaxf(m0, __shfl_xor_sync(~0u, m0, 2));
        m1 = fmaxf(m1, __shfl_xor_sync(~0u, m1, 1));
        m1 = fmaxf(m1, __shfl_xor_sync(~0u, m1, 2));
        float e[4][4];
        float s0 = 0.f, s1 = 0.f;
        #pragma unroll
        for (int nt = 0; nt < 4; nt++) {
            e[nt][0] = __expf(sacc[nt][0] - m0);
            e[nt][1] = __expf(sacc[nt][1] - m0);
            e[nt][2] = __expf(sacc[nt][2] - m1);
            e[nt][3] = __expf(sacc[nt][3] - m1);
            s0 += e[nt][0] + e[nt][1];
            s1 += e[nt][2] + e[nt][3];
        }
        s0 += __shfl_xor_sync(~0u, s0, 1); s0 += __shfl_xor_sync(~0u, s0, 2);
        s1 += __shfl_xor_sync(~0u, s1, 1); s1 += __shfl_xor_sync(~0u, s1, 2);
        if (tig == 0) {
            *(float2*)&Xc[(wh * 64 + mw + g) * 2]     = make_float2(m0, s0);
            *(float2*)&Xc[(wh * 64 + mw + g + 8) * 2] = make_float2(m1, s1);
        }
        __syncthreads();
        float2 o0 = *(float2*)&Xc[((1 ^ wh) * 64 + mw + g) * 2];
        float2 o1 = *(float2*)&Xc[((1 ^ wh) * 64 + mw + g + 8) * 2];
        float M0 = fmaxf(m0, o0.x);
        float sc0 = __expf(m0 - M0) / (s0 * __expf(m0 - M0) + o0.y * __expf(o0.x - M0));
        float M1 = fmaxf(m1, o1.x);
        float sc1 = __expf(m1 - M1) / (s1 * __expf(m1 - M1) + o1.y * __expf(o1.x - M1));
        {
            float* ao = attn_out + (size_t)((w * 3 + h) * 64) * 64;
            #pragma unroll
            for (int nt = 0; nt < 4; nt++) {
                int c = nw2 + nt * 8 + tig * 2;
                float p00 = e[nt][0] * sc0, p01 = e[nt][1] * sc0;
                float p10 = e[nt][2] * sc1, p11 = e[nt][3] * sc1;
                *(__nv_bfloat162*)&Ps[(mw + g) * 72 + c]     = __floats2bfloat162_rn(p00, p01);
                *(__nv_bfloat162*)&Ps[(mw + g + 8) * 72 + c] = __floats2bfloat162_rn(p10, p11);
                *(float2*)&ao[(size_t)(mw + g) * 64 + c]     = make_float2(p00, p01);
                *(float2*)&ao[(size_t)(mw + g + 8) * 64 + c] = make_float2(p10, p11);
            }
        }
        __syncthreads();

        // O = P @ V ; Os += (RMW onto lepe-init)
        {
            int d0 = h32 + wh * 16;
            float pacc[2][4] = {};
            #pragma unroll
            for (int ks = 0; ks < 4; ks++) {
                int kb = ks * 16;
                unsigned a[4];
                a[0] = *(const unsigned*)&Ps[(mw + g)     * 72 + kb + tig * 2];
                a[1] = *(const unsigned*)&Ps[(mw + g + 8) * 72 + kb + tig * 2];
                a[2] = *(const unsigned*)&Ps[(mw + g)     * 72 + kb + 8 + tig * 2];
                a[3] = *(const unsigned*)&Ps[(mw + g + 8) * 72 + kb + 8 + tig * 2];
                #pragma unroll
                for (int nt = 0; nt < 2; nt++) {
                    unsigned b[2];
                    int c0 = d0 + nt * 8 + g;
                    b[0] = *(const unsigned*)&Vt[c0 * 72 + kb + tig * 2];
                    b[1] = *(const unsigned*)&Vt[c0 * 72 + kb + 8 + tig * 2];
                    mma16(pacc[nt], a, b);
                }
            }
            #pragma unroll
            for (int nt = 0; nt < 2; nt++) {
                #pragma unroll
                for (int half = 0; half < 2; half++) {
                    int t = mw + g + half * 8;
                    #pragma unroll
                    for (int ee = 0; ee < 2; ee++) {
                        int d = d0 + nt * 8 + tig * 2 + ee;
                        float prev = __bfloat162float(Os[t * 100 + d]);
                        Os[t * 100 + d] =
                            __float2bfloat16(prev + pacc[nt][half * 2 + ee]);
                    }
                }
            }
        }
        __syncthreads();
    }

    // ---- phase 3: proj + residual(x) -> x1 staged in out gmem ----
    {
        float acc[2][3][4] = {};
        #pragma unroll
        for (int kq = 0; kq < 3; kq++) {
            uint4 b4[3];
            #pragma unroll
            for (int nt = 0; nt < 3; nt++) {
                int n8 = cgi * 3 + nt;
                b4[nt] = __ldg(&g_wproj_p4[(n8 * 3 + kq) * 32 + lane]);
            }
            #pragma unroll
            for (int kh = 0; kh < 2; kh++) {
                int kb = kq * 32 + kh * 16;
                unsigned a[2][4];
                #pragma unroll
                for (int mt = 0; mt < 2; mt++) {
                    int r = gm + mt * 16;
                    a[mt][0] = *(const unsigned*)&Os[(r + g)     * 100 + kb + tig * 2];
                    a[mt][1] = *(const unsigned*)&Os[(r + g + 8) * 100 + kb + tig * 2];
                    a[mt][2] = *(const unsigned*)&Os[(r + g)     * 100 + kb + 8 + tig * 2];
                    a[mt][3] = *(const unsigned*)&Os[(r + g + 8) * 100 + kb + 8 + tig * 2];
                }
                #pragma unroll
                for (int mt = 0; mt < 2; mt++)
                    #pragma unroll
                    for (int nt = 0; nt < 3; nt++)
                        mma16(acc[mt][nt], a[mt],
                              ((const unsigned*)&b4[nt]) + kh * 2);
            }
        }
        #pragma unroll
        for (int mt = 0; mt < 2; mt++) {
            #pragma unroll
            for (int half = 0; half < 2; half++) {
                int t = gm + mt * 16 + g + half * 8;
                int tok = win2tok(w * 64 + t);
                #pragma unroll
                for (int nt = 0; nt < 3; nt++) {
                    int c = gc + nt * 8 + tig * 2;
                    float2 xr = __ldg((const float2*)&x[(size_t)tok * 96 + c]);
                    float v0 = acc[mt][nt][half * 2 + 0] + bproj[c]     + xr.x;
                    float v1 = acc[mt][nt][half * 2 + 1] + bproj[c + 1] + xr.y;
                    *(float2*)(out + (size_t)tok * 96 + c) = make_float2(v0, v1);
                }
            }
        }
    }
    __syncthreads();

    // ---- phase 4a: LN2 (x1 rows from out gmem) -> As ----
    #pragma unroll
    for (int r = 0; r < 8; r++) {
        int t = wid * 8 + r;
        const float* xr = out + (size_t)win2tok(w * 64 + t) * 96;
        float v0 = xr[lane], v1 = xr[lane + 32], v2 = xr[lane + 64];
        float s = v0 + v1 + v2;
        #pragma unroll
        for (int o = 16; o; o >>= 1) s += __shfl_xor_sync(~0u, s, o);
        float m = s * (1.f / 96.f);
        float d0 = v0 - m, d1 = v1 - m, d2 = v2 - m;
        float q = d0 * d0 + d1 * d1 + d2 * d2;
        #pragma unroll
        for (int o = 16; o; o >>= 1) q += __shfl_xor_sync(~0u, q, o);
        float rr = rsqrtf(q * (1.f / 96.f) + 1e-5f);
        As[t * 100 + lane]      = __float2bfloat16(d0 * rr * g2[lane]      + bt2[lane]);
        As[t * 100 + lane + 32] = __float2bfloat16(d1 * rr * g2[lane + 32] + bt2[lane + 32]);
        As[t * 100 + lane + 64] = __float2bfloat16(d2 * rr * g2[lane + 64] + bt2[lane + 64]);
    }
    __syncthreads();

    // ---- phase 4b: MLP chunks ----
    float acc2[2][3][4] = {};
    for (int c = 0; c < 4; c++) {
        float accH[2][3][4] = {};
        #pragma unroll
        for (int kq = 0; kq < 3; kq++) {
            uint4 b4[3];
            #pragma unroll
            for (int nt = 0; nt < 3; nt++) {
                int n8 = c * 12 + cgi * 3 + nt;
                b4[nt] = __ldg(&g_w1_p4[(n8 * 3 + kq) * 32 + lane]);
            }
            #pragma unroll
            for (int kh = 0; kh < 2; kh++) {
                int kb = kq * 32 + kh * 16;
                unsigned a[2][4];
                #pragma unroll
                for (int mt = 0; mt < 2; mt++) {
                    int r = gm + mt * 16;
                    a[mt][0] = *(const unsigned*)&As[(r + g)     * 100 + kb + tig * 2];
                    a[mt][1] = *(const unsigned*)&As[(r + g + 8) * 100 + kb + tig * 2];
                    a[mt][2] = *(const unsigned*)&As[(r + g)     * 100 + kb + 8 + tig * 2];
                    a[mt][3] = *(const unsigned*)&As[(r + g + 8) * 100 + kb + 8 + tig * 2];
                }
                #pragma unroll
                for (int mt = 0; mt < 2; mt++)
                    #pragma unroll
                    for (int nt = 0; nt < 3; nt++)
                        mma16(accH[mt][nt], a[mt],
                              ((const unsigned*)&b4[nt]) + kh * 2);
            }
        }
        // bias1 + exact GELU -> Hs
        #pragma unroll
        for (int mt = 0; mt < 2; mt++) {
            #pragma unroll
            for (int half = 0; half < 2; half++) {
                int row = gm + mt * 16 + g + half * 8;
                #pragma unroll
                for (int nt = 0; nt < 3; nt++) {
                    int col = gc + nt * 8 + tig * 2;
                    float v0 = accH[mt][nt][half * 2 + 0] + b1[c * 96 + col];
                    float v1 = accH[mt][nt][half * 2 + 1] + b1[c * 96 + col + 1];
                    v0 = 0.5f * v0 * (1.f + erff(v0 * 0.70710678118f));
                    v1 = 0.5f * v1 * (1.f + erff(v1 * 0.70710678118f));
                    *(__nv_bfloat162*)&Hs[row * 100 + col] = __floats2bfloat162_rn(v0, v1);
                }
            }
        }
        __syncthreads();

        // acc2 += Hs @ W2c
        #pragma unroll
        for (int kq = 0; kq < 3; kq++) {
            uint4 b4[3];
            #pragma unroll
            for (int nt = 0; nt < 3; nt++) {
                int n8 = cgi * 3 + nt;
                b4[nt] = __ldg(&g_w2_p4[c * 1152 + (n8 * 3 + kq) * 32 + lane]);
            }
            #pragma unroll
            for (int kh = 0; kh < 2; kh++) {
                int kb = kq * 32 + kh * 16;
                unsigned a[2][4];
                #pragma unroll
                for (int mt = 0; mt < 2; mt++) {
                    int r = gm + mt * 16;
                    a[mt][0] = *(const unsigned*)&Hs[(r + g)     * 100 + kb + tig * 2];
                    a[mt][1] = *(const unsigned*)&Hs[(r + g + 8) * 100 + kb + tig * 2];
                    a[mt][2] = *(const unsigned*)&Hs[(r + g)     * 100 + kb + 8 + tig * 2];
                    a[mt][3] = *(const unsigned*)&Hs[(r + g + 8) * 100 + kb + 8 + tig * 2];
                }
                #pragma unroll
                for (int mt = 0; mt < 2; mt++)
                    #pragma unroll
                    for (int nt = 0; nt < 3; nt++)
                        mma16(acc2[mt][nt], a[mt],
                              ((const unsigned*)&b4[nt]) + kh * 2);
            }
        }
        __syncthreads();
    }

    // epilogue: out = x1(out gmem) + mlp + b2
    #pragma unroll
    for (int mt = 0; mt < 2; mt++) {
        #pragma unroll
        for (int half = 0; half < 2; half++) {
            int t = gm + mt * 16 + g + half * 8;
            int tok = win2tok(w * 64 + t);
            #pragma unroll
            for (int nt = 0; nt < 3; nt++) {
                int c = gc + nt * 8 + tig * 2;
                float2 x1r = __ldg((const float2*)&out[(size_t)tok * 96 + c]);
                float v0 = acc2[mt][nt][half * 2 + 0] + b2[c]     + x1r.x;
                float v1 = acc2[mt][nt][half * 2 + 1] + b2[c + 1] + x1r.y;
                *(float2*)(out + (size_t)tok * 96 + c) = make_float2(v0, v1);
            }
        }
    }
}

// ---------------- launch ----------------
extern "C" void kernel_launch(void* const* d_in, const int* in_sizes, int n_in,
                              void* d_out, int out_size) {
    const float* x      = (const float*)d_in[0];
    const float* w_qkv  = (const float*)d_in[1];
    const float* b_qkv  = (const float*)d_in[2];
    const float* w_lepe = (const float*)d_in[3];
    const float* b_lepe = (const float*)d_in[4];
    const float* w_proj = (const float*)d_in[5];
    const float* b_proj = (const float*)d_in[6];
    const float* g1     = (const float*)d_in[7];
    const float* bt1    = (const float*)d_in[8];
    const float* g2     = (const float*)d_in[9];
    const float* bt2    = (const float*)d_in[10];
    const float* w_fc1  = (const float*)d_in[11];
    const float* b_fc1  = (const float*)d_in[12];
    const float* w_fc2  = (const float*)d_in[13];
    const float* b_fc2  = (const float*)d_in[14];

    float* out0 = (float*)d_out;

    float* pfb;
    cudaGetSymbolAddress((void**)&pfb, g_attn_fb);

    float* attn_out = (out_size >= OUT0_ELEMS + ATTN_ELEMS)
                        ? (out0 + OUT0_ELEMS) : pfb;

    cudaFuncSetAttribute(block_kernel,
                         cudaFuncAttributeMaxDynamicSharedMemorySize, SM_TOT);

    // 0. pack weights into uint4 mma b-fragment order (13824 jobs)
    prep_weights<<<54, 256>>>(w_qkv, w_proj, w_fc1, w_fc2);

    // 1. fully fused transformer block, one window per block
    block_kernel<<<NW_N, 256, SM_TOT>>>(x, b_qkv, w_lepe, b_lepe, b_proj,
                                        g1, bt1, g2, bt2, b_fc1, b_fc2,
                                        out0, attn_out);
}